// round 5
// baseline (speedup 1.0000x reference)
#include <cuda_runtime.h>
#include <cstdint>

#define FULLMASK 0xffffffffu

constexpr int C      = 1024;   // columns per row
constexpr int KTOP   = 30;     // top-k
constexpr int WPB    = 8;      // warps (rows) per block
constexpr int MAXBLK = 32768;  // max grid blocks supported by partial arrays

// Per-block partial results (written unconditionally -> no zeroing needed).
__device__ float  g_match_part[MAXBLK];
__device__ double g_diff_part[MAXBLK];

__device__ __forceinline__ unsigned f2o(float f) {
    unsigned u = __float_as_uint(f);
    return (u & 0x80000000u) ? ~u : (u | 0x80000000u);
}
__device__ __forceinline__ float o2f(unsigned k) {
    unsigned u = (k & 0x80000000u) ? (k & 0x7fffffffu) : ~k;
    return __uint_as_float(u);
}
__device__ __forceinline__ unsigned umx(unsigned a, unsigned b) { return a > b ? a : b; }
__device__ __forceinline__ unsigned umn(unsigned a, unsigned b) { return a < b ? a : b; }

struct WarpScratch {
    unsigned keys[64];   // candidate keys (orderable u32)
    int      idx[2][32]; // top-30 index lists for tensor 0/1 (capacity 32)
    int      cnt;        // candidate counter
    int      cnt2;       // recovery counter
    int      pad[2];
};

// One bitonic compare-exchange phase on 64 elements (2 per lane: e0=lane, e1=lane+32).
// Descending sort overall.
#define PH(K_, J_) {                                                             \
    unsigned x0 = __shfl_xor_sync(FULLMASK, k0, (J_));                           \
    unsigned x1 = __shfl_xor_sync(FULLMASK, k1, (J_));                           \
    bool m0 = (((lane)      & (K_)) == 0) == (((lane)      & (J_)) == 0);        \
    bool m1 = ((((lane)+32) & (K_)) == 0) == ((((lane)+32) & (J_)) == 0);        \
    k0 = m0 ? umx(k0, x0) : umn(k0, x0);                                         \
    k1 = m1 ? umx(k1, x1) : umn(k1, x1);                                         \
}

// Processes one row of one tensor. Fills ws.idx[which][0..29] with the top-30
// column indices (unordered set) and returns, for lane l < 30, the l-th largest
// value of the row (exact fp32). Other lanes return 0.
__device__ __forceinline__ float process_row(const float* __restrict__ src,
                                             int row, int lane,
                                             WarpScratch& ws, int which) {
    const float NEG_INF = __int_as_float(0xff800000);
    float v[32];
    const float4* p = reinterpret_cast<const float4*>(src + (size_t)row * C);
#pragma unroll
    for (int q = 0; q < 8; q++) {
        float4 t = p[q * 32 + lane];
        v[q * 4 + 0] = t.x; v[q * 4 + 1] = t.y;
        v[q * 4 + 2] = t.z; v[q * 4 + 3] = t.w;
    }

    if (lane == 0) { ws.cnt = 0; ws.cnt2 = 0; }
    __syncwarp();

    // Gather candidates above fixed threshold (P(X>T0) ~ 45/1024 for N(0,1)).
    const float T0 = 1.7059f;
#pragma unroll
    for (int j = 0; j < 32; j++) {
        if (v[j] > T0) {
            int pos = atomicAdd(&ws.cnt, 1);
            if (pos < 64) ws.keys[pos] = f2o(v[j]);
        }
    }
    __syncwarp();
    int c = ws.cnt;

    unsigned k0 = 0, k1 = 0;

    if (c >= KTOP && c <= 64) {
        // --- fast path: bitonic sort 64 candidate keys, descending ---
        if (lane      >= c) ws.keys[lane]      = 0u;
        if (lane + 32 >= c) ws.keys[lane + 32] = 0u;
        __syncwarp();
        k0 = ws.keys[lane];
        k1 = ws.keys[lane + 32];

        PH(2, 1);
        PH(4, 2);  PH(4, 1);
        PH(8, 4);  PH(8, 2);  PH(8, 1);
        PH(16, 8); PH(16, 4); PH(16, 2); PH(16, 1);
        PH(32, 16); PH(32, 8); PH(32, 4); PH(32, 2); PH(32, 1);
        { unsigned a = umx(k0, k1), b = umn(k0, k1); k0 = a; k1 = b; } // k=64, j=32 (intra-lane)
        PH(64, 16); PH(64, 8); PH(64, 4); PH(64, 2); PH(64, 1);

        // lane l now holds the l-th largest key (l < 32) in k0.
        float vmin = o2f(__shfl_sync(FULLMASK, k0, KTOP - 1));

        // Index recovery: every element >= 30th value is a top-30 member.
#pragma unroll
        for (int j = 0; j < 32; j++) {
            if (v[j] >= vmin) {
                int pos = atomicAdd(&ws.cnt2, 1);
                if (pos < KTOP)
                    ws.idx[which][pos] = ((j >> 2) << 7) + (lane << 2) + (j & 3);
            }
        }
        __syncwarp();
    } else {
        // --- rare fallback: exact 30-step warp extraction ---
        float bestv = NEG_INF; int bestj = 0;
#pragma unroll
        for (int j = 0; j < 32; j++)
            if (v[j] > bestv) { bestv = v[j]; bestj = j; }

#pragma unroll 1
        for (int i = 0; i < KTOP; i++) {
            unsigned key = f2o(bestv);
            unsigned wk = key;
#pragma unroll
            for (int s = 16; s; s >>= 1)
                wk = umx(wk, __shfl_xor_sync(FULLMASK, wk, s));
            int winner = __ffs(__ballot_sync(FULLMASK, key == wk)) - 1;
            int gj = ((bestj >> 2) << 7) + (lane << 2) + (bestj & 3);
            int gwin = __shfl_sync(FULLMASK, gj, winner);
            if (lane == i) k0 = wk;
            if (lane == 0) ws.idx[which][i] = gwin;
            if (lane == winner) {
                float nb = NEG_INF; int nj = 0;
#pragma unroll
                for (int j = 0; j < 32; j++) {
                    float vj = (j == bestj) ? NEG_INF : v[j];
                    if (j == bestj) v[j] = NEG_INF;
                    if (vj > nb) { nb = vj; nj = j; }
                }
                bestv = nb; bestj = nj;
            }
            __syncwarp();
        }
    }

    return (lane < KTOP) ? o2f(k0) : 0.0f;
}

__global__ void __launch_bounds__(WPB * 32)
topk_main_kernel(const float* __restrict__ A, const float* __restrict__ B, int nrows) {
    __shared__ WarpScratch ws[WPB];
    __shared__ int   s_match[WPB];
    __shared__ float s_diff[WPB];

    int w = threadIdx.x >> 5;
    int lane = threadIdx.x & 31;
    int row = blockIdx.x * WPB + w;

    if (row < nrows) {
        float va = process_row(A, row, lane, ws[w], 0);
        float vb = process_row(B, row, lane, ws[w], 1);

        // diff: sum_k |v_pred[k] - v_topk[k]| for this row
        float d = (lane < KTOP) ? fabsf(va - vb) : 0.0f;
#pragma unroll
        for (int s = 16; s; s >>= 1)
            d += __shfl_xor_sync(FULLMASK, d, s);

        // match: |idx set A  ∩  idx set B|
        int ia = (lane < KTOP) ? ws[w].idx[0][lane] : -1;
        bool m = false;
#pragma unroll
        for (int j = 0; j < KTOP; j++) {
            int ib = ws[w].idx[1][j];   // same address for all lanes -> LDS broadcast
            m |= (ia == ib);
        }
        int mc = __popc(__ballot_sync(FULLMASK, m));

        if (lane == 0) { s_match[w] = mc; s_diff[w] = d; }
    } else {
        if (lane == 0) { s_match[w] = 0; s_diff[w] = 0.0f; }
    }

    __syncthreads();
    if (threadIdx.x == 0) {
        int mt = 0; double dt = 0.0;
#pragma unroll
        for (int i = 0; i < WPB; i++) { mt += s_match[i]; dt += (double)s_diff[i]; }
        g_match_part[blockIdx.x] = (float)mt;
        g_diff_part[blockIdx.x]  = dt;
    }
}

__global__ void topk_finalize_kernel(float* __restrict__ out, int nblocks, int nrows) {
    __shared__ double sm[256];
    __shared__ double sd[256];
    double m = 0.0, d = 0.0;
    for (int i = threadIdx.x; i < nblocks; i += blockDim.x) {
        m += (double)g_match_part[i];
        d += g_diff_part[i];
    }
    sm[threadIdx.x] = m;
    sd[threadIdx.x] = d;
    __syncthreads();
    for (int s = 128; s; s >>= 1) {
        if (threadIdx.x < s) {
            sm[threadIdx.x] += sm[threadIdx.x + s];
            sd[threadIdx.x] += sd[threadIdx.x + s];
        }
        __syncthreads();
    }
    if (threadIdx.x == 0) {
        out[0] = (float)(sm[0] / ((double)KTOP * (double)nrows)); // acc
        out[1] = (float)(sd[0] / (double)KTOP);                   // diff
    }
}

extern "C" void kernel_launch(void* const* d_in, const int* in_sizes, int n_in,
                              void* d_out, int out_size) {
    const float* A = (const float*)d_in[0];  // pred  (symmetric: order irrelevant)
    const float* B = (const float*)d_in[1];  // target
    int nrows = in_sizes[0] / C;
    int nblocks = (nrows + WPB - 1) / WPB;
    if (nblocks > MAXBLK) nblocks = MAXBLK;  // safety (not hit for B=131072)

    topk_main_kernel<<<nblocks, WPB * 32>>>(A, B, nrows);
    topk_finalize_kernel<<<1, 256>>>((float*)d_out, nblocks, nrows);
}